// round 8
// baseline (speedup 1.0000x reference)
#include <cuda_runtime.h>
#include <cuda_bf16.h>
#include <stdint.h>

// Problem constants
#define N_NODES 30000
#define N_EDGES 480000
#define K_SUB   32
#define P_PAIRS 16384
#define IN_DIM  1024
#define H_DIM   512
#define Z_DIM   128
#define BN_DIM  8
#define DB_DIM  16
#define DEC0_DIM 144   // Z + DB

// ---------------- scratch (static device globals; no allocation) -------------
__device__ float g_bufA [(size_t)N_NODES * H_DIM];
__device__ float g_bufB [(size_t)N_NODES * H_DIM];
__device__ float g_bufC [(size_t)N_NODES * H_DIM];
__device__ float g_bufC2[(size_t)N_NODES * H_DIM];
__device__ float g_bufD [(size_t)N_NODES * Z_DIM];
__device__ float g_bufD2[(size_t)N_NODES * Z_DIM];
__device__ float g_zn  [(size_t)N_NODES * Z_DIM];
__device__ float g_zn2 [(size_t)N_NODES * Z_DIM];
__device__ float g_be  [(size_t)N_NODES * DB_DIM];
__device__ float g_aggd[(size_t)N_NODES * DEC0_DIM];
__device__ int   g_cnt   [N_NODES];
__device__ int   g_start [N_NODES];
__device__ int   g_cursor[N_NODES];
__device__ int   g_csr   [N_EDGES];

// =============================================================================
// TF32 tensor-core GEMM: C[M,N] = A[M,K] @ B[K,N] (+bias)
// =============================================================================
#define GBM 128
#define GBN 128
#define GBK 32
#define ASTRIDE 36
#define BSTRIDE 136
#define GEMM_SMEM ((2*GBM*ASTRIDE + 2*GBK*BSTRIDE) * 4)

__device__ __forceinline__ uint32_t f2tf32(float x) {
    uint32_t r;
    asm("cvt.rna.tf32.f32 %0, %1;" : "=r"(r) : "f"(x));
    return r;
}

__global__ __launch_bounds__(256, 2)
void mma_gemm_kernel(int M, int Nn, int K,
                     const float* __restrict__ A, const float* __restrict__ B,
                     const float* __restrict__ bias, float* __restrict__ C)
{
    extern __shared__ float smem[];
    float* AsBase = smem;
    float* BsBase = smem + 2 * GBM * ASTRIDE;

    const int tid  = threadIdx.x;
    const int lane = tid & 31;
    const int wid  = tid >> 5;
    const int warpM = wid >> 2;
    const int warpN = wid & 3;
    const int grp   = lane >> 2;
    const int tig   = lane & 3;

    const int mBase = blockIdx.y * GBM;
    const int nBase = blockIdx.x * GBN;
    const int numStages = (K + GBK - 1) / GBK;

    float acc[4][4][4];
    #pragma unroll
    for (int i = 0; i < 4; i++)
        #pragma unroll
        for (int j = 0; j < 4; j++)
            #pragma unroll
            for (int r = 0; r < 4; r++) acc[i][j][r] = 0.f;

    auto loadStage = [&](int s, int buf) {
        float* Ab = AsBase + buf * GBM * ASTRIDE;
        float* Bb = BsBase + buf * GBK * BSTRIDE;
        const int k0 = s * GBK;
        #pragma unroll
        for (int i = 0; i < 4; i++) {
            int idx = tid + 256 * i;
            int row = idx >> 3;
            int c4  = idx & 7;
            int m = mBase + row;
            int k = k0 + c4 * 4;
            const float* g = A + (size_t)m * K + k;
            uint32_t saddr = (uint32_t)__cvta_generic_to_shared(Ab + row * ASTRIDE + c4 * 4);
            int ssz = (m < M && k < K) ? 16 : 0;
            asm volatile("cp.async.cg.shared.global [%0], [%1], 16, %2;\n"
                         :: "r"(saddr), "l"(g), "r"(ssz));
        }
        #pragma unroll
        for (int i = 0; i < 4; i++) {
            int idx = tid + 256 * i;
            int kr  = idx >> 5;
            int c4  = idx & 31;
            int k = k0 + kr;
            const float* g = B + (size_t)k * Nn + nBase + c4 * 4;
            uint32_t saddr = (uint32_t)__cvta_generic_to_shared(Bb + kr * BSTRIDE + c4 * 4);
            int ssz = (k < K) ? 16 : 0;
            asm volatile("cp.async.cg.shared.global [%0], [%1], 16, %2;\n"
                         :: "r"(saddr), "l"(g), "r"(ssz));
        }
        asm volatile("cp.async.commit_group;\n");
    };

    loadStage(0, 0);
    loadStage(1, 1);
    asm volatile("cp.async.wait_group 1;\n");
    __syncthreads();

    for (int s = 0; s < numStages; s++) {
        const int buf = s & 1;
        const float* Ab = AsBase + buf * GBM * ASTRIDE;
        const float* Bb = BsBase + buf * GBK * BSTRIDE;

        #pragma unroll
        for (int kt = 0; kt < 4; kt++) {
            const int kb = kt * 8;
            uint32_t afr[4][4], bfr[4][2];
            #pragma unroll
            for (int ni = 0; ni < 4; ni++) {
                int n0 = warpN * 32 + ni * 8 + grp;
                int kk = kb + tig;
                bfr[ni][0] = f2tf32(Bb[kk * BSTRIDE + n0]);
                bfr[ni][1] = f2tf32(Bb[(kk + 4) * BSTRIDE + n0]);
            }
            #pragma unroll
            for (int mi = 0; mi < 4; mi++) {
                int r0 = warpM * 64 + mi * 16 + grp;
                int kk = kb + tig;
                afr[mi][0] = f2tf32(Ab[r0 * ASTRIDE + kk]);
                afr[mi][1] = f2tf32(Ab[(r0 + 8) * ASTRIDE + kk]);
                afr[mi][2] = f2tf32(Ab[r0 * ASTRIDE + kk + 4]);
                afr[mi][3] = f2tf32(Ab[(r0 + 8) * ASTRIDE + kk + 4]);
            }
            #pragma unroll
            for (int mi = 0; mi < 4; mi++)
                #pragma unroll
                for (int ni = 0; ni < 4; ni++) {
                    asm volatile(
                        "mma.sync.aligned.m16n8k8.row.col.f32.tf32.tf32.f32 "
                        "{%0,%1,%2,%3}, {%4,%5,%6,%7}, {%8,%9}, {%0,%1,%2,%3};\n"
                        : "+f"(acc[mi][ni][0]), "+f"(acc[mi][ni][1]),
                          "+f"(acc[mi][ni][2]), "+f"(acc[mi][ni][3])
                        : "r"(afr[mi][0]), "r"(afr[mi][1]), "r"(afr[mi][2]), "r"(afr[mi][3]),
                          "r"(bfr[ni][0]), "r"(bfr[ni][1]));
                }
        }

        if (s + 1 < numStages) {
            if (s + 2 < numStages) {
                __syncthreads();
                loadStage(s + 2, buf);
                asm volatile("cp.async.wait_group 1;\n");
            } else {
                asm volatile("cp.async.wait_group 0;\n");
            }
            __syncthreads();
        }
    }

    #pragma unroll
    for (int mi = 0; mi < 4; mi++) {
        #pragma unroll
        for (int half = 0; half < 2; half++) {
            int m = mBase + warpM * 64 + mi * 16 + grp + half * 8;
            if (m < M) {
                #pragma unroll
                for (int ni = 0; ni < 4; ni++) {
                    int n = nBase + warpN * 32 + ni * 8 + 2 * tig;
                    float2 v = make_float2(acc[mi][ni][half * 2], acc[mi][ni][half * 2 + 1]);
                    if (bias) { v.x += bias[n]; v.y += bias[n + 1]; }
                    *(float2*)(C + (size_t)m * Nn + n) = v;
                }
            }
        }
    }
}

// =============================================================================
// CSR construction (by dst)
// =============================================================================
__global__ __launch_bounds__(256)
void hist_kernel(const int* __restrict__ dst, int* __restrict__ cnt, int E)
{
    int e = blockIdx.x * blockDim.x + threadIdx.x;
    if (e < E) atomicAdd(&cnt[dst[e]], 1);
}

#define SCAN_PER 30   // ceil(30000/1024)
__global__ __launch_bounds__(1024)
void scan_kernel(const int* __restrict__ cnt, int* __restrict__ start,
                 int* __restrict__ cursor, int n)
{
    __shared__ int part[1024];
    int t = threadIdx.x;
    int base = t * SCAN_PER;
    int s = 0;
    for (int i = 0; i < SCAN_PER; i++) {
        int idx = base + i;
        if (idx < n) s += cnt[idx];
    }
    part[t] = s;
    __syncthreads();
    for (int off = 1; off < 1024; off <<= 1) {
        int v = (t >= off) ? part[t - off] : 0;
        __syncthreads();
        part[t] += v;
        __syncthreads();
    }
    int run = part[t] - s;   // exclusive prefix for this thread's chunk
    for (int i = 0; i < SCAN_PER; i++) {
        int idx = base + i;
        if (idx < n) {
            start[idx] = run;
            cursor[idx] = run;
            run += cnt[idx];
        }
    }
}

__global__ __launch_bounds__(256)
void scatter_kernel(const int* __restrict__ src, const int* __restrict__ dst,
                    int* __restrict__ cursor, int* __restrict__ csr, int E)
{
    int e = blockIdx.x * blockDim.x + threadIdx.x;
    if (e >= E) return;
    int pos = atomicAdd(&cursor[dst[e]], 1);
    csr[pos] = src[e];
}

// =============================================================================
// Fused dual-path GIN aggregation + bias + LN + ReLU. Warp per node.
// =============================================================================
template<int D>
__global__ __launch_bounds__(256)
void gin_agg_dual_kernel(const float* __restrict__ X1, const float* __restrict__ X2,
                         const int* __restrict__ start, const int* __restrict__ cnt,
                         const int* __restrict__ csr,
                         const float* __restrict__ bias,
                         float* __restrict__ out1, float* __restrict__ out2,
                         int Nrows)
{
    constexpr int C4 = D / 4;
    constexpr int V  = C4 / 32;
    int w = (int)((blockIdx.x * (long long)blockDim.x + threadIdx.x) >> 5);
    if (w >= Nrows) return;
    int lane = threadIdx.x & 31;

    float4 a1[V], a2[V];
    #pragma unroll
    for (int v = 0; v < V; v++) {
        int c = (lane + v * 32) * 4;
        a1[v] = *(const float4*)(X1 + (size_t)w * D + c);
        a2[v] = *(const float4*)(X2 + (size_t)w * D + c);
    }

    int s0  = start[w];
    int deg = cnt[w];
    for (int base = 0; base < deg; base += 32) {
        int rem = deg - base;
        int myid = (lane < rem) ? csr[s0 + base + lane] : 0;
        int m = rem < 32 ? rem : 32;
        for (int k = 0; k < m; k++) {
            int j = __shfl_sync(0xffffffffu, myid, k);
            const float* r1 = X1 + (size_t)j * D;
            const float* r2 = X2 + (size_t)j * D;
            #pragma unroll
            for (int v = 0; v < V; v++) {
                int c = (lane + v * 32) * 4;
                float4 t1 = *(const float4*)(r1 + c);
                float4 t2 = *(const float4*)(r2 + c);
                a1[v].x += t1.x; a1[v].y += t1.y; a1[v].z += t1.z; a1[v].w += t1.w;
                a2[v].x += t2.x; a2[v].y += t2.y; a2[v].z += t2.z; a2[v].w += t2.w;
            }
        }
    }

    float s1 = 0.f, q1 = 0.f, s2 = 0.f, q2 = 0.f;
    #pragma unroll
    for (int v = 0; v < V; v++) {
        int c = (lane + v * 32) * 4;
        float4 b = *(const float4*)(bias + c);
        a1[v].x += b.x; a1[v].y += b.y; a1[v].z += b.z; a1[v].w += b.w;
        a2[v].x += b.x; a2[v].y += b.y; a2[v].z += b.z; a2[v].w += b.w;
        s1 += a1[v].x + a1[v].y + a1[v].z + a1[v].w;
        q1 += a1[v].x*a1[v].x + a1[v].y*a1[v].y + a1[v].z*a1[v].z + a1[v].w*a1[v].w;
        s2 += a2[v].x + a2[v].y + a2[v].z + a2[v].w;
        q2 += a2[v].x*a2[v].x + a2[v].y*a2[v].y + a2[v].z*a2[v].z + a2[v].w*a2[v].w;
    }
    #pragma unroll
    for (int off = 16; off; off >>= 1) {
        s1 += __shfl_xor_sync(0xffffffffu, s1, off);
        q1 += __shfl_xor_sync(0xffffffffu, q1, off);
        s2 += __shfl_xor_sync(0xffffffffu, s2, off);
        q2 += __shfl_xor_sync(0xffffffffu, q2, off);
    }
    float m1 = s1 / D, m2 = s2 / D;
    float i1 = rsqrtf(q1 / D - m1 * m1 + 1e-5f);
    float i2 = rsqrtf(q2 / D - m2 * m2 + 1e-5f);
    #pragma unroll
    for (int v = 0; v < V; v++) {
        int c = (lane + v * 32) * 4;
        float4 o1 = make_float4(fmaxf((a1[v].x - m1) * i1, 0.f), fmaxf((a1[v].y - m1) * i1, 0.f),
                                fmaxf((a1[v].z - m1) * i1, 0.f), fmaxf((a1[v].w - m1) * i1, 0.f));
        float4 o2 = make_float4(fmaxf((a2[v].x - m2) * i2, 0.f), fmaxf((a2[v].y - m2) * i2, 0.f),
                                fmaxf((a2[v].z - m2) * i2, 0.f), fmaxf((a2[v].w - m2) * i2, 0.f));
        *(float4*)(out1 + (size_t)w * D + c) = o1;
        *(float4*)(out2 + (size_t)w * D + c) = o2;
    }
}

// ---- single-path agg (no LN), unrolled by 2 neighbors; for decoder L1 -------
template<int D>
__global__ __launch_bounds__(256)
void gin_agg_kernel(const float* __restrict__ X,
                    const int* __restrict__ start, const int* __restrict__ cnt,
                    const int* __restrict__ csr,
                    float* __restrict__ out, int Nrows)
{
    constexpr int C4 = D / 4;
    constexpr int V  = C4 / 32;
    int w = (int)((blockIdx.x * (long long)blockDim.x + threadIdx.x) >> 5);
    if (w >= Nrows) return;
    int lane = threadIdx.x & 31;

    float4 acc[V];
    #pragma unroll
    for (int v = 0; v < V; v++)
        acc[v] = *(const float4*)(X + (size_t)w * D + (lane + v * 32) * 4);

    int s0  = start[w];
    int deg = cnt[w];
    for (int base = 0; base < deg; base += 32) {
        int rem = deg - base;
        int myid = (lane < rem) ? csr[s0 + base + lane] : 0;
        int m = rem < 32 ? rem : 32;
        int k = 0;
        for (; k + 2 <= m; k += 2) {
            int j0 = __shfl_sync(0xffffffffu, myid, k);
            int j1 = __shfl_sync(0xffffffffu, myid, k + 1);
            const float* r0 = X + (size_t)j0 * D;
            const float* r1 = X + (size_t)j1 * D;
            #pragma unroll
            for (int v = 0; v < V; v++) {
                int c = (lane + v * 32) * 4;
                float4 t0 = *(const float4*)(r0 + c);
                float4 t1 = *(const float4*)(r1 + c);
                acc[v].x += t0.x + t1.x; acc[v].y += t0.y + t1.y;
                acc[v].z += t0.z + t1.z; acc[v].w += t0.w + t1.w;
            }
        }
        if (k < m) {
            int j = __shfl_sync(0xffffffffu, myid, k);
            const float* r = X + (size_t)j * D;
            #pragma unroll
            for (int v = 0; v < V; v++) {
                int c = (lane + v * 32) * 4;
                float4 t = *(const float4*)(r + c);
                acc[v].x += t.x; acc[v].y += t.y; acc[v].z += t.z; acc[v].w += t.w;
            }
        }
    }

    #pragma unroll
    for (int v = 0; v < V; v++)
        *(float4*)(out + (size_t)w * D + (lane + v * 32) * 4) = acc[v];
}

// ---- decoder L0: fused concat(zn|be) + agg -> aggd[144] ---------------------
__global__ __launch_bounds__(256)
void gin_agg_dec0_kernel(const float* __restrict__ zn, const float* __restrict__ be,
                         const int* __restrict__ start, const int* __restrict__ cnt,
                         const int* __restrict__ csr,
                         float* __restrict__ out, int Nrows)
{
    int w = (int)((blockIdx.x * (long long)blockDim.x + threadIdx.x) >> 5);
    if (w >= Nrows) return;
    int lane = threadIdx.x & 31;
    float4 accZ = *(const float4*)(zn + (size_t)w * Z_DIM + lane * 4);
    float4 accB = make_float4(0.f, 0.f, 0.f, 0.f);
    if (lane < 4) accB = *(const float4*)(be + (size_t)w * DB_DIM + lane * 4);

    int s0  = start[w];
    int deg = cnt[w];
    for (int base = 0; base < deg; base += 32) {
        int rem = deg - base;
        int myid = (lane < rem) ? csr[s0 + base + lane] : 0;
        int m = rem < 32 ? rem : 32;
        for (int k = 0; k < m; k++) {
            int j = __shfl_sync(0xffffffffu, myid, k);
            float4 t = *(const float4*)(zn + (size_t)j * Z_DIM + lane * 4);
            accZ.x += t.x; accZ.y += t.y; accZ.z += t.z; accZ.w += t.w;
            if (lane < 4) {
                float4 u = *(const float4*)(be + (size_t)j * DB_DIM + lane * 4);
                accB.x += u.x; accB.y += u.y; accB.z += u.z; accB.w += u.w;
            }
        }
    }
    *(float4*)(out + (size_t)w * DEC0_DIM + lane * 4) = accZ;
    if (lane < 4)
        *(float4*)(out + (size_t)w * DEC0_DIM + Z_DIM + lane * 4) = accB;
}

// ---------------- fused (Y + bias) -> LayerNorm -> ReLU ----------------------
template<int D>
__global__ __launch_bounds__(256)
void ln_relu_kernel(const float* __restrict__ Y, const float* __restrict__ bias,
                    float* __restrict__ out, int Nrows)
{
    constexpr int V = D / 128;
    int w = (int)((blockIdx.x * (long long)blockDim.x + threadIdx.x) >> 5);
    if (w >= Nrows) return;
    int lane = threadIdx.x & 31;

    float4 v[V];
    float s = 0.f, sq = 0.f;
    #pragma unroll
    for (int i = 0; i < V; i++) {
        int c = (lane + i * 32) * 4;
        float4 y = *(const float4*)(Y + (size_t)w * D + c);
        float4 b = *(const float4*)(bias + c);
        y.x += b.x; y.y += b.y; y.z += b.z; y.w += b.w;
        v[i] = y;
        s  += y.x + y.y + y.z + y.w;
        sq += y.x*y.x + y.y*y.y + y.z*y.z + y.w*y.w;
    }
    #pragma unroll
    for (int off = 16; off; off >>= 1) {
        s  += __shfl_xor_sync(0xffffffffu, s,  off);
        sq += __shfl_xor_sync(0xffffffffu, sq, off);
    }
    float mean = s / D;
    float inv  = rsqrtf(sq / D - mean * mean + 1e-5f);
    #pragma unroll
    for (int i = 0; i < V; i++) {
        int c = (lane + i * 32) * 4;
        float4 y = v[i];
        y.x = fmaxf((y.x - mean) * inv, 0.f);
        y.y = fmaxf((y.y - mean) * inv, 0.f);
        y.z = fmaxf((y.z - mean) * inv, 0.f);
        y.w = fmaxf((y.w - mean) * inv, 0.f);
        *(float4*)(out + (size_t)w * D + c) = y;
    }
}

// ---------------- dual subgraph mean pool (K=32, Z=128) ----------------------
__global__ __launch_bounds__(256)
void pool_dual_kernel(const float* __restrict__ z1, const float* __restrict__ z2,
                      const int* __restrict__ idx,
                      float* __restrict__ o1, float* __restrict__ o2, int Nrows)
{
    int w = (int)((blockIdx.x * (long long)blockDim.x + threadIdx.x) >> 5);
    if (w >= Nrows) return;
    int lane = threadIdx.x & 31;
    int myidx = __ldg(&idx[(size_t)w * 32 + lane]);
    float4 a1 = make_float4(0.f, 0.f, 0.f, 0.f);
    float4 a2 = make_float4(0.f, 0.f, 0.f, 0.f);
    #pragma unroll
    for (int k = 0; k < 32; k++) {
        int j = __shfl_sync(0xffffffffu, myidx, k);
        float4 v1 = *(const float4*)(z1 + (size_t)j * 128 + lane * 4);
        float4 v2 = *(const float4*)(z2 + (size_t)j * 128 + lane * 4);
        a1.x += v1.x; a1.y += v1.y; a1.z += v1.z; a1.w += v1.w;
        a2.x += v2.x; a2.y += v2.y; a2.z += v2.z; a2.w += v2.w;
    }
    const float inv = 1.f / 32.f;
    a1.x *= inv; a1.y *= inv; a1.z *= inv; a1.w *= inv;
    a2.x *= inv; a2.y *= inv; a2.z *= inv; a2.w *= inv;
    *(float4*)(o1 + (size_t)w * 128 + lane * 4) = a1;
    *(float4*)(o2 + (size_t)w * 128 + lane * 4) = a2;
}

// ---------------- batch encoder MLP (8 -> 12 relu -> 16) ---------------------
__global__ __launch_bounds__(256)
void be_kernel(const float* __restrict__ bl,
               const float* __restrict__ W0, const float* __restrict__ b0,
               const float* __restrict__ W1, const float* __restrict__ b1,
               float* __restrict__ out, int Nr)
{
    int n = blockIdx.x * blockDim.x + threadIdx.x;
    if (n >= Nr) return;
    float in[8];
    #pragma unroll
    for (int i = 0; i < 8; i++) in[i] = bl[(size_t)n * 8 + i];
    float h[12];
    #pragma unroll
    for (int j = 0; j < 12; j++) {
        float s = b0[j];
        #pragma unroll
        for (int i = 0; i < 8; i++) s += in[i] * W0[i * 12 + j];
        h[j] = fmaxf(s, 0.f);
    }
    #pragma unroll
    for (int j = 0; j < 16; j++) {
        float s = b1[j];
        #pragma unroll
        for (int i = 0; i < 12; i++) s += h[i] * W1[i * 16 + j];
        out[(size_t)n * 16 + j] = s;
    }
}

// ---------------- batch discriminator: weights in smem, warp/node ------------
#define BD_BLOCKS 128
__global__ __launch_bounds__(256)
void bd_kernel(const float* __restrict__ zs,
               const float* __restrict__ W0, const float* __restrict__ b0,
               const float* __restrict__ W1, const float* __restrict__ b1,
               float* __restrict__ out, int Nr)
{
    __shared__ float W0s[128 * 64];   // 32 KB
    __shared__ float W1s[64 * 8];
    __shared__ float b0s[64];
    int tid = threadIdx.x;
    for (int i = tid; i < 128 * 64; i += 256) W0s[i] = W0[i];
    for (int i = tid; i < 64 * 8;  i += 256) W1s[i] = W1[i];
    if (tid < 64) b0s[tid] = b0[tid];
    __syncthreads();

    int lane = tid & 31;
    int warp = tid >> 5;
    int gw   = blockIdx.x * 8 + warp;   // global warp
    const int NW = BD_BLOCKS * 8;

    for (int n = gw; n < Nr; n += NW) {
        float zr[4];
        #pragma unroll
        for (int r = 0; r < 4; r++) zr[r] = zs[(size_t)n * 128 + r * 32 + lane];

        float h0 = b0s[lane], h1 = b0s[32 + lane];
        #pragma unroll 4
        for (int d = 0; d < 128; d++) {
            float zd = __shfl_sync(0xffffffffu, zr[d >> 5], d & 31);
            h0 += zd * W0s[d * 64 + lane];
            h1 += zd * W0s[d * 64 + 32 + lane];
        }
        h0 = fmaxf(h0, 0.f);
        h1 = fmaxf(h1, 0.f);

        float p[8];
        #pragma unroll
        for (int j = 0; j < 8; j++)
            p[j] = h0 * W1s[lane * 8 + j] + h1 * W1s[(32 + lane) * 8 + j];
        #pragma unroll
        for (int off = 16; off; off >>= 1)
            #pragma unroll
            for (int j = 0; j < 8; j++)
                p[j] += __shfl_xor_sync(0xffffffffu, p[j], off);
        if (lane < 8)
            out[(size_t)n * 8 + lane] = p[lane] + b1[lane];
    }
}

// ---------------- bilinear logits via precomputed Y = z_sub @ W --------------
__global__ __launch_bounds__(256)
void bil_dot_kernel(const float* __restrict__ Y, const float* __restrict__ zss,
                    const int* __restrict__ pos, const int* __restrict__ neg,
                    float* __restrict__ lp, float* __restrict__ ln_, int P)
{
    int w = (int)((blockIdx.x * (long long)blockDim.x + threadIdx.x) >> 5);
    if (w >= P) return;
    int lane = threadIdx.x & 31;
    int pi = __ldg(&pos[w]);
    int ni = __ldg(&neg[w]);
    float4 y = *(const float4*)(Y   + (size_t)pi * 128 + lane * 4);
    float4 a = *(const float4*)(zss + (size_t)pi * 128 + lane * 4);
    float4 b = *(const float4*)(zss + (size_t)ni * 128 + lane * 4);
    float sp = y.x * a.x + y.y * a.y + y.z * a.z + y.w * a.w;
    float sn = y.x * b.x + y.y * b.y + y.z * b.z + y.w * b.w;
    #pragma unroll
    for (int off = 16; off; off >>= 1) {
        sp += __shfl_xor_sync(0xffffffffu, sp, off);
        sn += __shfl_xor_sync(0xffffffffu, sn, off);
    }
    if (lane == 0) { lp[w] = sp; ln_[w] = sn; }
}

// =============================================================================
extern "C" void kernel_launch(void* const* d_in, const int* in_sizes, int n_in,
                              void* d_out, int out_size)
{
    const float* x      = (const float*)d_in[0];
    const float* x_shf  = (const float*)d_in[1];
    const float* bl     = (const float*)d_in[2];
    const float* enc_W0 = (const float*)d_in[3];
    const float* enc_b0 = (const float*)d_in[4];
    const float* enc_W1 = (const float*)d_in[5];
    const float* enc_b1 = (const float*)d_in[6];
    const float* dec_W0 = (const float*)d_in[7];
    const float* dec_b0 = (const float*)d_in[8];
    const float* dec_W1 = (const float*)d_in[9];
    const float* dec_b1 = (const float*)d_in[10];
    const float* be_W0  = (const float*)d_in[11];
    const float* be_b0  = (const float*)d_in[12];
    const float* be_W1  = (const float*)d_in[13];
    const float* be_b1  = (const float*)d_in[14];
    const float* bd_W0  = (const float*)d_in[15];
    const float* bd_b0  = (const float*)d_in[16];
    const float* bd_W1  = (const float*)d_in[17];
    const float* bd_b1  = (const float*)d_in[18];
    const float* bil_W  = (const float*)d_in[19];
    const int*   edge   = (const int*)d_in[20];
    const int*   subidx = (const int*)d_in[21];
    const int*   pos    = (const int*)d_in[22];
    const int*   neg    = (const int*)d_in[23];

    const int* src = edge;
    const int* dst = edge + N_EDGES;

    static float *bufA=nullptr,*bufB,*bufC,*bufC2,*bufD,*bufD2,*zn,*zn2,*be,*aggd;
    static int *cnt,*startp,*cursor,*csr;
    static bool attr_done = false;
    if (!bufA) {
        cudaGetSymbolAddress((void**)&bufA,  g_bufA);
        cudaGetSymbolAddress((void**)&bufB,  g_bufB);
        cudaGetSymbolAddress((void**)&bufC,  g_bufC);
        cudaGetSymbolAddress((void**)&bufC2, g_bufC2);
        cudaGetSymbolAddress((void**)&bufD,  g_bufD);
        cudaGetSymbolAddress((void**)&bufD2, g_bufD2);
        cudaGetSymbolAddress((void**)&zn,    g_zn);
        cudaGetSymbolAddress((void**)&zn2,   g_zn2);
        cudaGetSymbolAddress((void**)&be,    g_be);
        cudaGetSymbolAddress((void**)&aggd,  g_aggd);
        cudaGetSymbolAddress((void**)&cnt,    g_cnt);
        cudaGetSymbolAddress((void**)&startp, g_start);
        cudaGetSymbolAddress((void**)&cursor, g_cursor);
        cudaGetSymbolAddress((void**)&csr,    g_csr);
    }
    if (!attr_done) {
        cudaFuncSetAttribute(mma_gemm_kernel,
                             cudaFuncAttributeMaxDynamicSharedMemorySize, GEMM_SMEM);
        attr_done = true;
    }

    float* out       = (float*)d_out;
    float* o_zsub    = out;
    float* o_zsubshf = out + (size_t)N_NODES * Z_DIM;
    float* o_recon   = out + 2ull * N_NODES * Z_DIM;
    float* o_lp      = o_recon + (size_t)N_NODES * IN_DIM;
    float* o_ln      = o_lp + P_PAIRS;
    float* o_lb      = o_ln + P_PAIRS;

    const int MB = (N_NODES + GBM - 1) / GBM;

    auto gemm = [&](int M, int Nn, int K, const float* A, const float* B,
                    const float* bias, float* C) {
        dim3 grid(Nn / GBN, MB);
        mma_gemm_kernel<<<grid, 256, GEMM_SMEM>>>(M, Nn, K, A, B, bias, C);
    };

    // ---- CSR build (reused by all aggregations) ----
    cudaMemsetAsync(cnt, 0, N_NODES * sizeof(int), 0);
    hist_kernel<<<(N_EDGES + 255) / 256, 256>>>(dst, cnt, N_EDGES);
    scan_kernel<<<1, 1024>>>(cnt, startp, cursor, N_NODES);
    scatter_kernel<<<(N_EDGES + 255) / 256, 256>>>(src, dst, cursor, csr, N_EDGES);

    const int AGG_GRID = (N_NODES * 32 + 255) / 256;

    // ---- encoder, both paths ----
    gemm(N_NODES, H_DIM, IN_DIM, x,     enc_W0, nullptr, bufA);
    gemm(N_NODES, H_DIM, IN_DIM, x_shf, enc_W0, nullptr, bufB);
    gin_agg_dual_kernel<H_DIM><<<AGG_GRID, 256>>>(bufA, bufB, startp, cnt, csr,
                                                  enc_b0, bufC, bufC2, N_NODES);
    gemm(N_NODES, Z_DIM, H_DIM, bufC,  enc_W1, nullptr, bufD);
    gemm(N_NODES, Z_DIM, H_DIM, bufC2, enc_W1, nullptr, bufD2);
    gin_agg_dual_kernel<Z_DIM><<<AGG_GRID, 256>>>(bufD, bufD2, startp, cnt, csr,
                                                  enc_b1, zn, zn2, N_NODES);
    pool_dual_kernel<<<AGG_GRID, 256>>>(zn, zn2, subidx, o_zsub, o_zsubshf, N_NODES);

    // batch encoder MLP
    be_kernel<<<(N_NODES + 255) / 256, 256>>>(bl, be_W0, be_b0, be_W1, be_b1, be, N_NODES);

    // batch discriminator (weights cached in smem)
    bd_kernel<<<BD_BLOCKS, 256>>>(o_zsub, bd_W0, bd_b0, bd_W1, bd_b1, o_lb, N_NODES);

    // bilinear logits: Y = z_sub @ W (tf32 GEMM), then warp dot products
    gemm(N_NODES, Z_DIM, Z_DIM, o_zsub, bil_W, nullptr, bufD);
    bil_dot_kernel<<<(P_PAIRS * 32 + 255) / 256, 256>>>(bufD, o_zsubshf, pos, neg,
                                                        o_lp, o_ln, P_PAIRS);

    // dec layer 0: fused concat+agg in 144-space, then GEMM + LN + relu
    gin_agg_dec0_kernel<<<AGG_GRID, 256>>>(zn, be, startp, cnt, csr, aggd, N_NODES);
    gemm(N_NODES, H_DIM, DEC0_DIM, aggd, dec_W0, nullptr, bufA);
    ln_relu_kernel<H_DIM><<<AGG_GRID, 256>>>(bufA, dec_b0, bufC, N_NODES);

    // dec layer 1: agg in H-space, GEMM + bias -> recon
    gin_agg_kernel<H_DIM><<<AGG_GRID, 256>>>(bufC, startp, cnt, csr, bufB, N_NODES);
    gemm(N_NODES, IN_DIM, H_DIM, bufB, dec_W1, dec_b1, o_recon);
}

// round 9
// speedup vs baseline: 1.5409x; 1.5409x over previous
#include <cuda_runtime.h>
#include <cuda_bf16.h>
#include <stdint.h>

// Problem constants
#define N_NODES 30000
#define N_EDGES 480000
#define K_SUB   32
#define P_PAIRS 16384
#define IN_DIM  1024
#define H_DIM   512
#define Z_DIM   128
#define BN_DIM  8
#define DB_DIM  16
#define DEC0_DIM 144   // Z + DB

// ---------------- scratch (static device globals; no allocation) -------------
__device__ float g_bufA[(size_t)N_NODES * H_DIM];
__device__ float g_bufB[(size_t)N_NODES * H_DIM];
__device__ float g_bufC[(size_t)N_NODES * H_DIM];
__device__ float g_bufD[(size_t)N_NODES * Z_DIM];
__device__ float g_zn  [(size_t)N_NODES * Z_DIM];
__device__ float g_zn2 [(size_t)N_NODES * Z_DIM];
__device__ float g_be  [(size_t)N_NODES * DB_DIM];
__device__ float g_aggd[(size_t)N_NODES * DEC0_DIM];
__device__ int   g_cnt   [N_NODES];
__device__ int   g_start [N_NODES];
__device__ int   g_cursor[N_NODES];
__device__ int   g_csr   [N_EDGES];

// =============================================================================
// TF32 tensor-core GEMM: C[M,N] = A[M,K] @ B[K,N] (+bias)
// =============================================================================
#define GBM 128
#define GBN 128
#define GBK 32
#define ASTRIDE 36
#define BSTRIDE 136
#define GEMM_SMEM ((2*GBM*ASTRIDE + 2*GBK*BSTRIDE) * 4)

__device__ __forceinline__ uint32_t f2tf32(float x) {
    uint32_t r;
    asm("cvt.rna.tf32.f32 %0, %1;" : "=r"(r) : "f"(x));
    return r;
}

__global__ __launch_bounds__(256, 2)
void mma_gemm_kernel(int M, int Nn, int K,
                     const float* __restrict__ A, const float* __restrict__ B,
                     const float* __restrict__ bias, float* __restrict__ C)
{
    extern __shared__ float smem[];
    float* AsBase = smem;
    float* BsBase = smem + 2 * GBM * ASTRIDE;

    const int tid  = threadIdx.x;
    const int lane = tid & 31;
    const int wid  = tid >> 5;
    const int warpM = wid >> 2;
    const int warpN = wid & 3;
    const int grp   = lane >> 2;
    const int tig   = lane & 3;

    const int mBase = blockIdx.y * GBM;
    const int nBase = blockIdx.x * GBN;
    const int numStages = (K + GBK - 1) / GBK;

    float acc[4][4][4];
    #pragma unroll
    for (int i = 0; i < 4; i++)
        #pragma unroll
        for (int j = 0; j < 4; j++)
            #pragma unroll
            for (int r = 0; r < 4; r++) acc[i][j][r] = 0.f;

    auto loadStage = [&](int s, int buf) {
        float* Ab = AsBase + buf * GBM * ASTRIDE;
        float* Bb = BsBase + buf * GBK * BSTRIDE;
        const int k0 = s * GBK;
        #pragma unroll
        for (int i = 0; i < 4; i++) {
            int idx = tid + 256 * i;
            int row = idx >> 3;
            int c4  = idx & 7;
            int m = mBase + row;
            int k = k0 + c4 * 4;
            const float* g = A + (size_t)m * K + k;
            uint32_t saddr = (uint32_t)__cvta_generic_to_shared(Ab + row * ASTRIDE + c4 * 4);
            int ssz = (m < M && k < K) ? 16 : 0;
            asm volatile("cp.async.cg.shared.global [%0], [%1], 16, %2;\n"
                         :: "r"(saddr), "l"(g), "r"(ssz));
        }
        #pragma unroll
        for (int i = 0; i < 4; i++) {
            int idx = tid + 256 * i;
            int kr  = idx >> 5;
            int c4  = idx & 31;
            int k = k0 + kr;
            const float* g = B + (size_t)k * Nn + nBase + c4 * 4;
            uint32_t saddr = (uint32_t)__cvta_generic_to_shared(Bb + kr * BSTRIDE + c4 * 4);
            int ssz = (k < K) ? 16 : 0;
            asm volatile("cp.async.cg.shared.global [%0], [%1], 16, %2;\n"
                         :: "r"(saddr), "l"(g), "r"(ssz));
        }
        asm volatile("cp.async.commit_group;\n");
    };

    loadStage(0, 0);
    loadStage(1, 1);
    asm volatile("cp.async.wait_group 1;\n");
    __syncthreads();

    for (int s = 0; s < numStages; s++) {
        const int buf = s & 1;
        const float* Ab = AsBase + buf * GBM * ASTRIDE;
        const float* Bb = BsBase + buf * GBK * BSTRIDE;

        #pragma unroll
        for (int kt = 0; kt < 4; kt++) {
            const int kb = kt * 8;
            uint32_t afr[4][4], bfr[4][2];
            #pragma unroll
            for (int ni = 0; ni < 4; ni++) {
                int n0 = warpN * 32 + ni * 8 + grp;
                int kk = kb + tig;
                bfr[ni][0] = f2tf32(Bb[kk * BSTRIDE + n0]);
                bfr[ni][1] = f2tf32(Bb[(kk + 4) * BSTRIDE + n0]);
            }
            #pragma unroll
            for (int mi = 0; mi < 4; mi++) {
                int r0 = warpM * 64 + mi * 16 + grp;
                int kk = kb + tig;
                afr[mi][0] = f2tf32(Ab[r0 * ASTRIDE + kk]);
                afr[mi][1] = f2tf32(Ab[(r0 + 8) * ASTRIDE + kk]);
                afr[mi][2] = f2tf32(Ab[r0 * ASTRIDE + kk + 4]);
                afr[mi][3] = f2tf32(Ab[(r0 + 8) * ASTRIDE + kk + 4]);
            }
            #pragma unroll
            for (int mi = 0; mi < 4; mi++)
                #pragma unroll
                for (int ni = 0; ni < 4; ni++) {
                    asm volatile(
                        "mma.sync.aligned.m16n8k8.row.col.f32.tf32.tf32.f32 "
                        "{%0,%1,%2,%3}, {%4,%5,%6,%7}, {%8,%9}, {%0,%1,%2,%3};\n"
                        : "+f"(acc[mi][ni][0]), "+f"(acc[mi][ni][1]),
                          "+f"(acc[mi][ni][2]), "+f"(acc[mi][ni][3])
                        : "r"(afr[mi][0]), "r"(afr[mi][1]), "r"(afr[mi][2]), "r"(afr[mi][3]),
                          "r"(bfr[ni][0]), "r"(bfr[ni][1]));
                }
        }

        if (s + 1 < numStages) {
            if (s + 2 < numStages) {
                __syncthreads();
                loadStage(s + 2, buf);
                asm volatile("cp.async.wait_group 1;\n");
            } else {
                asm volatile("cp.async.wait_group 0;\n");
            }
            __syncthreads();
        }
    }

    #pragma unroll
    for (int mi = 0; mi < 4; mi++) {
        #pragma unroll
        for (int half = 0; half < 2; half++) {
            int m = mBase + warpM * 64 + mi * 16 + grp + half * 8;
            if (m < M) {
                #pragma unroll
                for (int ni = 0; ni < 4; ni++) {
                    int n = nBase + warpN * 32 + ni * 8 + 2 * tig;
                    float2 v = make_float2(acc[mi][ni][half * 2], acc[mi][ni][half * 2 + 1]);
                    if (bias) { v.x += bias[n]; v.y += bias[n + 1]; }
                    *(float2*)(C + (size_t)m * Nn + n) = v;
                }
            }
        }
    }
}

// =============================================================================
// CSR construction (by dst)
// =============================================================================
__global__ __launch_bounds__(256)
void hist_kernel(const int* __restrict__ dst, int* __restrict__ cnt, int E)
{
    int e = blockIdx.x * blockDim.x + threadIdx.x;
    if (e < E) atomicAdd(&cnt[dst[e]], 1);
}

#define SCAN_PER 30   // ceil(30000/1024)
__global__ __launch_bounds__(1024)
void scan_kernel(const int* __restrict__ cnt, int* __restrict__ start,
                 int* __restrict__ cursor, int n)
{
    __shared__ int part[1024];
    int t = threadIdx.x;
    int base = t * SCAN_PER;
    int s = 0;
    for (int i = 0; i < SCAN_PER; i++) {
        int idx = base + i;
        if (idx < n) s += cnt[idx];
    }
    part[t] = s;
    __syncthreads();
    for (int off = 1; off < 1024; off <<= 1) {
        int v = (t >= off) ? part[t - off] : 0;
        __syncthreads();
        part[t] += v;
        __syncthreads();
    }
    int run = part[t] - s;   // exclusive prefix for this thread's chunk
    for (int i = 0; i < SCAN_PER; i++) {
        int idx = base + i;
        if (idx < n) {
            start[idx] = run;
            cursor[idx] = run;
            run += cnt[idx];
        }
    }
}

__global__ __launch_bounds__(256)
void scatter_kernel(const int* __restrict__ src, const int* __restrict__ dst,
                    int* __restrict__ cursor, int* __restrict__ csr, int E)
{
    int e = blockIdx.x * blockDim.x + threadIdx.x;
    if (e >= E) return;
    int pos = atomicAdd(&cursor[dst[e]], 1);
    csr[pos] = src[e];
}

// =============================================================================
// Fused GIN aggregation (single path, as R3): warp per node.
// out[i] = f( X[i] + sum_{j in N(i)} X[j] [+bias] ), f = LN+ReLU if LNR.
// =============================================================================
template<int D, bool LNR>
__global__ __launch_bounds__(256)
void gin_agg_kernel(const float* __restrict__ X,
                    const int* __restrict__ start, const int* __restrict__ cnt,
                    const int* __restrict__ csr,
                    const float* __restrict__ bias,
                    float* __restrict__ out, int Nrows)
{
    constexpr int C4 = D / 4;
    constexpr int V  = (C4 + 31) / 32;
    int w = (int)((blockIdx.x * (long long)blockDim.x + threadIdx.x) >> 5);
    if (w >= Nrows) return;
    int lane = threadIdx.x & 31;

    float4 acc[V];
    #pragma unroll
    for (int v = 0; v < V; v++) {
        int c4 = lane + v * 32;
        if (c4 < C4) acc[v] = *(const float4*)(X + (size_t)w * D + c4 * 4);
        else         acc[v] = make_float4(0.f, 0.f, 0.f, 0.f);
    }

    int s0  = start[w];
    int deg = cnt[w];
    for (int base = 0; base < deg; base += 32) {
        int rem = deg - base;
        int myid = (lane < rem) ? csr[s0 + base + lane] : 0;
        int m = rem < 32 ? rem : 32;
        for (int k = 0; k < m; k++) {
            int j = __shfl_sync(0xffffffffu, myid, k);
            const float* row = X + (size_t)j * D;
            #pragma unroll
            for (int v = 0; v < V; v++) {
                int c4 = lane + v * 32;
                if (c4 < C4) {
                    float4 t = *(const float4*)(row + c4 * 4);
                    acc[v].x += t.x; acc[v].y += t.y; acc[v].z += t.z; acc[v].w += t.w;
                }
            }
        }
    }

    if (LNR) {
        float s = 0.f, sq = 0.f;
        #pragma unroll
        for (int v = 0; v < V; v++) {
            int c4 = lane + v * 32;
            if (c4 < C4) {
                float4 b = *(const float4*)(bias + c4 * 4);
                acc[v].x += b.x; acc[v].y += b.y; acc[v].z += b.z; acc[v].w += b.w;
                s  += acc[v].x + acc[v].y + acc[v].z + acc[v].w;
                sq += acc[v].x*acc[v].x + acc[v].y*acc[v].y
                    + acc[v].z*acc[v].z + acc[v].w*acc[v].w;
            }
        }
        #pragma unroll
        for (int off = 16; off; off >>= 1) {
            s  += __shfl_xor_sync(0xffffffffu, s,  off);
            sq += __shfl_xor_sync(0xffffffffu, sq, off);
        }
        float mean = s / D;
        float var  = sq / D - mean * mean;
        float inv  = rsqrtf(var + 1e-5f);
        #pragma unroll
        for (int v = 0; v < V; v++) {
            acc[v].x = fmaxf((acc[v].x - mean) * inv, 0.f);
            acc[v].y = fmaxf((acc[v].y - mean) * inv, 0.f);
            acc[v].z = fmaxf((acc[v].z - mean) * inv, 0.f);
            acc[v].w = fmaxf((acc[v].w - mean) * inv, 0.f);
        }
    }

    #pragma unroll
    for (int v = 0; v < V; v++) {
        int c4 = lane + v * 32;
        if (c4 < C4) *(float4*)(out + (size_t)w * D + c4 * 4) = acc[v];
    }
}

// ---- decoder L0: fused concat(zn|be) + agg -> aggd[144] ---------------------
__global__ __launch_bounds__(256)
void gin_agg_dec0_kernel(const float* __restrict__ zn, const float* __restrict__ be,
                         const int* __restrict__ start, const int* __restrict__ cnt,
                         const int* __restrict__ csr,
                         float* __restrict__ out, int Nrows)
{
    int w = (int)((blockIdx.x * (long long)blockDim.x + threadIdx.x) >> 5);
    if (w >= Nrows) return;
    int lane = threadIdx.x & 31;
    float4 accZ = *(const float4*)(zn + (size_t)w * Z_DIM + lane * 4);
    float4 accB = make_float4(0.f, 0.f, 0.f, 0.f);
    if (lane < 4) accB = *(const float4*)(be + (size_t)w * DB_DIM + lane * 4);

    int s0  = start[w];
    int deg = cnt[w];
    for (int base = 0; base < deg; base += 32) {
        int rem = deg - base;
        int myid = (lane < rem) ? csr[s0 + base + lane] : 0;
        int m = rem < 32 ? rem : 32;
        for (int k = 0; k < m; k++) {
            int j = __shfl_sync(0xffffffffu, myid, k);
            float4 t = *(const float4*)(zn + (size_t)j * Z_DIM + lane * 4);
            accZ.x += t.x; accZ.y += t.y; accZ.z += t.z; accZ.w += t.w;
            if (lane < 4) {
                float4 u = *(const float4*)(be + (size_t)j * DB_DIM + lane * 4);
                accB.x += u.x; accB.y += u.y; accB.z += u.z; accB.w += u.w;
            }
        }
    }
    *(float4*)(out + (size_t)w * DEC0_DIM + lane * 4) = accZ;
    if (lane < 4)
        *(float4*)(out + (size_t)w * DEC0_DIM + Z_DIM + lane * 4) = accB;
}

// ---------------- fused (Y + bias) -> LayerNorm -> ReLU ----------------------
template<int D>
__global__ __launch_bounds__(256)
void ln_relu_kernel(const float* __restrict__ Y, const float* __restrict__ bias,
                    float* __restrict__ out, int Nrows)
{
    constexpr int V = D / 128;
    int w = (int)((blockIdx.x * (long long)blockDim.x + threadIdx.x) >> 5);
    if (w >= Nrows) return;
    int lane = threadIdx.x & 31;

    float4 v[V];
    float s = 0.f, sq = 0.f;
    #pragma unroll
    for (int i = 0; i < V; i++) {
        int c = (lane + i * 32) * 4;
        float4 y = *(const float4*)(Y + (size_t)w * D + c);
        float4 b = *(const float4*)(bias + c);
        y.x += b.x; y.y += b.y; y.z += b.z; y.w += b.w;
        v[i] = y;
        s  += y.x + y.y + y.z + y.w;
        sq += y.x*y.x + y.y*y.y + y.z*y.z + y.w*y.w;
    }
    #pragma unroll
    for (int off = 16; off; off >>= 1) {
        s  += __shfl_xor_sync(0xffffffffu, s,  off);
        sq += __shfl_xor_sync(0xffffffffu, sq, off);
    }
    float mean = s / D;
    float inv  = rsqrtf(sq / D - mean * mean + 1e-5f);
    #pragma unroll
    for (int i = 0; i < V; i++) {
        int c = (lane + i * 32) * 4;
        float4 y = v[i];
        y.x = fmaxf((y.x - mean) * inv, 0.f);
        y.y = fmaxf((y.y - mean) * inv, 0.f);
        y.z = fmaxf((y.z - mean) * inv, 0.f);
        y.w = fmaxf((y.w - mean) * inv, 0.f);
        *(float4*)(out + (size_t)w * D + c) = y;
    }
}

// ---------------- subgraph mean pool (K=32, Z=128): warp per node ------------
__global__ __launch_bounds__(256)
void pool_kernel(const float* __restrict__ zn, const int* __restrict__ idx,
                 float* __restrict__ out, int Nrows)
{
    int w = (int)((blockIdx.x * (long long)blockDim.x + threadIdx.x) >> 5);
    if (w >= Nrows) return;
    int lane = threadIdx.x & 31;
    int myidx = __ldg(&idx[(size_t)w * 32 + lane]);
    float4 acc = make_float4(0.f, 0.f, 0.f, 0.f);
    #pragma unroll
    for (int k = 0; k < 32; k++) {
        int j = __shfl_sync(0xffffffffu, myidx, k);
        float4 v = *(const float4*)(zn + (size_t)j * 128 + lane * 4);
        acc.x += v.x; acc.y += v.y; acc.z += v.z; acc.w += v.w;
    }
    const float inv = 1.f / 32.f;
    acc.x *= inv; acc.y *= inv; acc.z *= inv; acc.w *= inv;
    *(float4*)(out + (size_t)w * 128 + lane * 4) = acc;
}

// ---------------- batch encoder MLP (8 -> 12 relu -> 16) ---------------------
__global__ __launch_bounds__(256)
void be_kernel(const float* __restrict__ bl,
               const float* __restrict__ W0, const float* __restrict__ b0,
               const float* __restrict__ W1, const float* __restrict__ b1,
               float* __restrict__ out, int Nr)
{
    int n = blockIdx.x * blockDim.x + threadIdx.x;
    if (n >= Nr) return;
    float in[8];
    #pragma unroll
    for (int i = 0; i < 8; i++) in[i] = bl[(size_t)n * 8 + i];
    float h[12];
    #pragma unroll
    for (int j = 0; j < 12; j++) {
        float s = b0[j];
        #pragma unroll
        for (int i = 0; i < 8; i++) s += in[i] * W0[i * 12 + j];
        h[j] = fmaxf(s, 0.f);
    }
    #pragma unroll
    for (int j = 0; j < 16; j++) {
        float s = b1[j];
        #pragma unroll
        for (int i = 0; i < 12; i++) s += h[i] * W1[i * 16 + j];
        out[(size_t)n * 16 + j] = s;
    }
}

// ---------------- batch discriminator: weights in smem, warp/node ------------
#define BD_BLOCKS 128
__global__ __launch_bounds__(256)
void bd_kernel(const float* __restrict__ zs,
               const float* __restrict__ W0, const float* __restrict__ b0,
               const float* __restrict__ W1, const float* __restrict__ b1,
               float* __restrict__ out, int Nr)
{
    __shared__ float W0s[128 * 64];   // 32 KB
    __shared__ float W1s[64 * 8];
    __shared__ float b0s[64];
    int tid = threadIdx.x;
    for (int i = tid; i < 128 * 64; i += 256) W0s[i] = W0[i];
    for (int i = tid; i < 64 * 8;  i += 256) W1s[i] = W1[i];
    if (tid < 64) b0s[tid] = b0[tid];
    __syncthreads();

    int lane = tid & 31;
    int warp = tid >> 5;
    int gw   = blockIdx.x * 8 + warp;   // global warp
    const int NW = BD_BLOCKS * 8;

    for (int n = gw; n < Nr; n += NW) {
        float zr[4];
        #pragma unroll
        for (int r = 0; r < 4; r++) zr[r] = zs[(size_t)n * 128 + r * 32 + lane];

        float h0 = b0s[lane], h1 = b0s[32 + lane];
        #pragma unroll 4
        for (int d = 0; d < 128; d++) {
            float zd = __shfl_sync(0xffffffffu, zr[d >> 5], d & 31);
            h0 += zd * W0s[d * 64 + lane];
            h1 += zd * W0s[d * 64 + 32 + lane];
        }
        h0 = fmaxf(h0, 0.f);
        h1 = fmaxf(h1, 0.f);

        float p[8];
        #pragma unroll
        for (int j = 0; j < 8; j++)
            p[j] = h0 * W1s[lane * 8 + j] + h1 * W1s[(32 + lane) * 8 + j];
        #pragma unroll
        for (int off = 16; off; off >>= 1)
            #pragma unroll
            for (int j = 0; j < 8; j++)
                p[j] += __shfl_xor_sync(0xffffffffu, p[j], off);
        if (lane < 8)
            out[(size_t)n * 8 + lane] = p[lane] + b1[lane];
    }
}

// ---------------- bilinear logits via precomputed Y = z_sub @ W --------------
__global__ __launch_bounds__(256)
void bil_dot_kernel(const float* __restrict__ Y, const float* __restrict__ zss,
                    const int* __restrict__ pos, const int* __restrict__ neg,
                    float* __restrict__ lp, float* __restrict__ ln_, int P)
{
    int w = (int)((blockIdx.x * (long long)blockDim.x + threadIdx.x) >> 5);
    if (w >= P) return;
    int lane = threadIdx.x & 31;
    int pi = __ldg(&pos[w]);
    int ni = __ldg(&neg[w]);
    float4 y = *(const float4*)(Y   + (size_t)pi * 128 + lane * 4);
    float4 a = *(const float4*)(zss + (size_t)pi * 128 + lane * 4);
    float4 b = *(const float4*)(zss + (size_t)ni * 128 + lane * 4);
    float sp = y.x * a.x + y.y * a.y + y.z * a.z + y.w * a.w;
    float sn = y.x * b.x + y.y * b.y + y.z * b.z + y.w * b.w;
    #pragma unroll
    for (int off = 16; off; off >>= 1) {
        sp += __shfl_xor_sync(0xffffffffu, sp, off);
        sn += __shfl_xor_sync(0xffffffffu, sn, off);
    }
    if (lane == 0) { lp[w] = sp; ln_[w] = sn; }
}

// =============================================================================
extern "C" void kernel_launch(void* const* d_in, const int* in_sizes, int n_in,
                              void* d_out, int out_size)
{
    const float* x      = (const float*)d_in[0];
    const float* x_shf  = (const float*)d_in[1];
    const float* bl     = (const float*)d_in[2];
    const float* enc_W0 = (const float*)d_in[3];
    const float* enc_b0 = (const float*)d_in[4];
    const float* enc_W1 = (const float*)d_in[5];
    const float* enc_b1 = (const float*)d_in[6];
    const float* dec_W0 = (const float*)d_in[7];
    const float* dec_b0 = (const float*)d_in[8];
    const float* dec_W1 = (const float*)d_in[9];
    const float* dec_b1 = (const float*)d_in[10];
    const float* be_W0  = (const float*)d_in[11];
    const float* be_b0  = (const float*)d_in[12];
    const float* be_W1  = (const float*)d_in[13];
    const float* be_b1  = (const float*)d_in[14];
    const float* bd_W0  = (const float*)d_in[15];
    const float* bd_b0  = (const float*)d_in[16];
    const float* bd_W1  = (const float*)d_in[17];
    const float* bd_b1  = (const float*)d_in[18];
    const float* bil_W  = (const float*)d_in[19];
    const int*   edge   = (const int*)d_in[20];
    const int*   subidx = (const int*)d_in[21];
    const int*   pos    = (const int*)d_in[22];
    const int*   neg    = (const int*)d_in[23];

    const int* src = edge;
    const int* dst = edge + N_EDGES;

    static float *bufA=nullptr,*bufB,*bufC,*bufD,*zn,*zn2,*be,*aggd;
    static int *cnt,*startp,*cursor,*csr;
    static bool attr_done = false;
    if (!bufA) {
        cudaGetSymbolAddress((void**)&bufA,  g_bufA);
        cudaGetSymbolAddress((void**)&bufB,  g_bufB);
        cudaGetSymbolAddress((void**)&bufC,  g_bufC);
        cudaGetSymbolAddress((void**)&bufD,  g_bufD);
        cudaGetSymbolAddress((void**)&zn,    g_zn);
        cudaGetSymbolAddress((void**)&zn2,   g_zn2);
        cudaGetSymbolAddress((void**)&be,    g_be);
        cudaGetSymbolAddress((void**)&aggd,  g_aggd);
        cudaGetSymbolAddress((void**)&cnt,    g_cnt);
        cudaGetSymbolAddress((void**)&startp, g_start);
        cudaGetSymbolAddress((void**)&cursor, g_cursor);
        cudaGetSymbolAddress((void**)&csr,    g_csr);
    }
    if (!attr_done) {
        cudaFuncSetAttribute(mma_gemm_kernel,
                             cudaFuncAttributeMaxDynamicSharedMemorySize, GEMM_SMEM);
        attr_done = true;
    }

    float* out       = (float*)d_out;
    float* o_zsub    = out;
    float* o_zsubshf = out + (size_t)N_NODES * Z_DIM;
    float* o_recon   = out + 2ull * N_NODES * Z_DIM;
    float* o_lp      = o_recon + (size_t)N_NODES * IN_DIM;
    float* o_ln      = o_lp + P_PAIRS;
    float* o_lb      = o_ln + P_PAIRS;

    const int MB = (N_NODES + GBM - 1) / GBM;

    auto gemm = [&](int M, int Nn, int K, const float* A, const float* B,
                    const float* bias, float* C) {
        dim3 grid(Nn / GBN, MB);
        mma_gemm_kernel<<<grid, 256, GEMM_SMEM>>>(M, Nn, K, A, B, bias, C);
    };

    // ---- CSR build (reused by all aggregations) ----
    cudaMemsetAsync(cnt, 0, N_NODES * sizeof(int), 0);
    hist_kernel<<<(N_EDGES + 255) / 256, 256>>>(dst, cnt, N_EDGES);
    scan_kernel<<<1, 1024>>>(cnt, startp, cursor, N_NODES);
    scatter_kernel<<<(N_EDGES + 255) / 256, 256>>>(src, dst, cursor, csr, N_EDGES);

    const int AGG_GRID = (N_NODES * 32 + 255) / 256;

    // ---- encoder (x 2 paths, single-path aggs as R3) ----
    auto encode = [&](const float* xin, float* z_out, float* pool_out) {
        gemm(N_NODES, H_DIM, IN_DIM, xin, enc_W0, nullptr, bufA);
        gin_agg_kernel<H_DIM, true><<<AGG_GRID, 256>>>(bufA, startp, cnt, csr, enc_b0, bufC, N_NODES);
        gemm(N_NODES, Z_DIM, H_DIM, bufC, enc_W1, nullptr, bufD);
        gin_agg_kernel<Z_DIM, true><<<AGG_GRID, 256>>>(bufD, startp, cnt, csr, enc_b1, z_out, N_NODES);
        pool_kernel<<<AGG_GRID, 256>>>(z_out, subidx, pool_out, N_NODES);
    };

    encode(x,     zn,  o_zsub);
    encode(x_shf, zn2, o_zsubshf);

    // batch encoder MLP
    be_kernel<<<(N_NODES + 255) / 256, 256>>>(bl, be_W0, be_b0, be_W1, be_b1, be, N_NODES);

    // batch discriminator (weights cached in smem)
    bd_kernel<<<BD_BLOCKS, 256>>>(o_zsub, bd_W0, bd_b0, bd_W1, bd_b1, o_lb, N_NODES);

    // bilinear logits: Y = z_sub @ W (tf32 GEMM), then warp dot products
    gemm(N_NODES, Z_DIM, Z_DIM, o_zsub, bil_W, nullptr, bufD);
    bil_dot_kernel<<<(P_PAIRS * 32 + 255) / 256, 256>>>(bufD, o_zsubshf, pos, neg,
                                                        o_lp, o_ln, P_PAIRS);

    // dec layer 0: fused concat+agg in 144-space, then GEMM + LN + relu
    gin_agg_dec0_kernel<<<AGG_GRID, 256>>>(zn, be, startp, cnt, csr, aggd, N_NODES);
    gemm(N_NODES, H_DIM, DEC0_DIM, aggd, dec_W0, nullptr, bufA);
    ln_relu_kernel<H_DIM><<<AGG_GRID, 256>>>(bufA, dec_b0, bufC, N_NODES);

    // dec layer 1: agg in H-space, GEMM + bias -> recon
    gin_agg_kernel<H_DIM, false><<<AGG_GRID, 256>>>(bufC, startp, cnt, csr, nullptr, bufB, N_NODES);
    gemm(N_NODES, IN_DIM, H_DIM, bufB, dec_W1, dec_b1, o_recon);
}

// round 11
// speedup vs baseline: 1.6864x; 1.0944x over previous
#include <cuda_runtime.h>
#include <cuda_bf16.h>
#include <stdint.h>

// Problem constants
#define N_NODES 30000
#define N_EDGES 480000
#define K_SUB   32
#define P_PAIRS 16384
#define IN_DIM  1024
#define H_DIM   512
#define Z_DIM   128
#define BN_DIM  8
#define DB_DIM  16
#define DEC0_DIM 144   // Z + DB

// ---------------- scratch (static device globals; no allocation) -------------
__device__ float g_bufA [(size_t)N_NODES * H_DIM];   // enc p1 L0 out / dec L0 gemm out
__device__ float g_bufB [(size_t)N_NODES * H_DIM];   // enc p2 L0 out / dec L1 agg out
__device__ float g_bufC [(size_t)N_NODES * H_DIM];   // enc p1 h / dec ln out
__device__ float g_bufC2[(size_t)N_NODES * H_DIM];   // enc p2 h
__device__ float g_bufD [(size_t)N_NODES * Z_DIM];   // enc p1 L1 gemm out / bil Y
__device__ float g_bufD2[(size_t)N_NODES * Z_DIM];   // enc p2 L1 gemm out
__device__ float g_zn  [(size_t)N_NODES * Z_DIM];
__device__ float g_zn2 [(size_t)N_NODES * Z_DIM];
__device__ float g_be  [(size_t)N_NODES * DB_DIM];
__device__ float g_aggd[(size_t)N_NODES * DEC0_DIM];
__device__ int   g_cnt   [N_NODES];
__device__ int   g_start [N_NODES];
__device__ int   g_cursor[N_NODES];
__device__ int   g_csr   [N_EDGES];

// =============================================================================
// TF32 tensor-core GEMM: C[M,N] = A[M,K] @ B[K,N] (+bias)
// =============================================================================
#define GBM 128
#define GBN 128
#define GBK 32
#define ASTRIDE 36
#define BSTRIDE 136
#define GEMM_SMEM ((2*GBM*ASTRIDE + 2*GBK*BSTRIDE) * 4)

__device__ __forceinline__ uint32_t f2tf32(float x) {
    uint32_t r;
    asm("cvt.rna.tf32.f32 %0, %1;" : "=r"(r) : "f"(x));
    return r;
}

__global__ __launch_bounds__(256, 2)
void mma_gemm_kernel(int M, int Nn, int K,
                     const float* __restrict__ A, const float* __restrict__ B,
                     const float* __restrict__ bias, float* __restrict__ C)
{
    extern __shared__ float smem[];
    float* AsBase = smem;
    float* BsBase = smem + 2 * GBM * ASTRIDE;

    const int tid  = threadIdx.x;
    const int lane = tid & 31;
    const int wid  = tid >> 5;
    const int warpM = wid >> 2;
    const int warpN = wid & 3;
    const int grp   = lane >> 2;
    const int tig   = lane & 3;

    const int mBase = blockIdx.y * GBM;
    const int nBase = blockIdx.x * GBN;
    const int numStages = (K + GBK - 1) / GBK;

    float acc[4][4][4];
    #pragma unroll
    for (int i = 0; i < 4; i++)
        #pragma unroll
        for (int j = 0; j < 4; j++)
            #pragma unroll
            for (int r = 0; r < 4; r++) acc[i][j][r] = 0.f;

    auto loadStage = [&](int s, int buf) {
        float* Ab = AsBase + buf * GBM * ASTRIDE;
        float* Bb = BsBase + buf * GBK * BSTRIDE;
        const int k0 = s * GBK;
        #pragma unroll
        for (int i = 0; i < 4; i++) {
            int idx = tid + 256 * i;
            int row = idx >> 3;
            int c4  = idx & 7;
            int m = mBase + row;
            int k = k0 + c4 * 4;
            const float* g = A + (size_t)m * K + k;
            uint32_t saddr = (uint32_t)__cvta_generic_to_shared(Ab + row * ASTRIDE + c4 * 4);
            int ssz = (m < M && k < K) ? 16 : 0;
            asm volatile("cp.async.cg.shared.global [%0], [%1], 16, %2;\n"
                         :: "r"(saddr), "l"(g), "r"(ssz));
        }
        #pragma unroll
        for (int i = 0; i < 4; i++) {
            int idx = tid + 256 * i;
            int kr  = idx >> 5;
            int c4  = idx & 31;
            int k = k0 + kr;
            const float* g = B + (size_t)k * Nn + nBase + c4 * 4;
            uint32_t saddr = (uint32_t)__cvta_generic_to_shared(Bb + kr * BSTRIDE + c4 * 4);
            int ssz = (k < K) ? 16 : 0;
            asm volatile("cp.async.cg.shared.global [%0], [%1], 16, %2;\n"
                         :: "r"(saddr), "l"(g), "r"(ssz));
        }
        asm volatile("cp.async.commit_group;\n");
    };

    loadStage(0, 0);
    loadStage(1, 1);
    asm volatile("cp.async.wait_group 1;\n");
    __syncthreads();

    for (int s = 0; s < numStages; s++) {
        const int buf = s & 1;
        const float* Ab = AsBase + buf * GBM * ASTRIDE;
        const float* Bb = BsBase + buf * GBK * BSTRIDE;

        #pragma unroll
        for (int kt = 0; kt < 4; kt++) {
            const int kb = kt * 8;
            uint32_t afr[4][4], bfr[4][2];
            #pragma unroll
            for (int ni = 0; ni < 4; ni++) {
                int n0 = warpN * 32 + ni * 8 + grp;
                int kk = kb + tig;
                bfr[ni][0] = f2tf32(Bb[kk * BSTRIDE + n0]);
                bfr[ni][1] = f2tf32(Bb[(kk + 4) * BSTRIDE + n0]);
            }
            #pragma unroll
            for (int mi = 0; mi < 4; mi++) {
                int r0 = warpM * 64 + mi * 16 + grp;
                int kk = kb + tig;
                afr[mi][0] = f2tf32(Ab[r0 * ASTRIDE + kk]);
                afr[mi][1] = f2tf32(Ab[(r0 + 8) * ASTRIDE + kk]);
                afr[mi][2] = f2tf32(Ab[r0 * ASTRIDE + kk + 4]);
                afr[mi][3] = f2tf32(Ab[(r0 + 8) * ASTRIDE + kk + 4]);
            }
            #pragma unroll
            for (int mi = 0; mi < 4; mi++)
                #pragma unroll
                for (int ni = 0; ni < 4; ni++) {
                    asm volatile(
                        "mma.sync.aligned.m16n8k8.row.col.f32.tf32.tf32.f32 "
                        "{%0,%1,%2,%3}, {%4,%5,%6,%7}, {%8,%9}, {%0,%1,%2,%3};\n"
                        : "+f"(acc[mi][ni][0]), "+f"(acc[mi][ni][1]),
                          "+f"(acc[mi][ni][2]), "+f"(acc[mi][ni][3])
                        : "r"(afr[mi][0]), "r"(afr[mi][1]), "r"(afr[mi][2]), "r"(afr[mi][3]),
                          "r"(bfr[ni][0]), "r"(bfr[ni][1]));
                }
        }

        if (s + 1 < numStages) {
            if (s + 2 < numStages) {
                __syncthreads();
                loadStage(s + 2, buf);
                asm volatile("cp.async.wait_group 1;\n");
            } else {
                asm volatile("cp.async.wait_group 0;\n");
            }
            __syncthreads();
        }
    }

    #pragma unroll
    for (int mi = 0; mi < 4; mi++) {
        #pragma unroll
        for (int half = 0; half < 2; half++) {
            int m = mBase + warpM * 64 + mi * 16 + grp + half * 8;
            if (m < M) {
                #pragma unroll
                for (int ni = 0; ni < 4; ni++) {
                    int n = nBase + warpN * 32 + ni * 8 + 2 * tig;
                    float2 v = make_float2(acc[mi][ni][half * 2], acc[mi][ni][half * 2 + 1]);
                    if (bias) { v.x += bias[n]; v.y += bias[n + 1]; }
                    *(float2*)(C + (size_t)m * Nn + n) = v;
                }
            }
        }
    }
}

// =============================================================================
// CSR construction (by dst)
// =============================================================================
__global__ __launch_bounds__(256)
void hist_kernel(const int* __restrict__ dst, int* __restrict__ cnt, int E)
{
    int e = blockIdx.x * blockDim.x + threadIdx.x;
    if (e < E) atomicAdd(&cnt[dst[e]], 1);
}

#define SCAN_PER 30   // ceil(30000/1024)
__global__ __launch_bounds__(1024)
void scan_kernel(const int* __restrict__ cnt, int* __restrict__ start,
                 int* __restrict__ cursor, int n)
{
    __shared__ int part[1024];
    int t = threadIdx.x;
    int base = t * SCAN_PER;
    int s = 0;
    for (int i = 0; i < SCAN_PER; i++) {
        int idx = base + i;
        if (idx < n) s += cnt[idx];
    }
    part[t] = s;
    __syncthreads();
    for (int off = 1; off < 1024; off <<= 1) {
        int v = (t >= off) ? part[t - off] : 0;
        __syncthreads();
        part[t] += v;
        __syncthreads();
    }
    int run = part[t] - s;
    for (int i = 0; i < SCAN_PER; i++) {
        int idx = base + i;
        if (idx < n) {
            start[idx] = run;
            cursor[idx] = run;
            run += cnt[idx];
        }
    }
}

__global__ __launch_bounds__(256)
void scatter_kernel(const int* __restrict__ src, const int* __restrict__ dst,
                    int* __restrict__ cursor, int* __restrict__ csr, int E)
{
    int e = blockIdx.x * blockDim.x + threadIdx.x;
    if (e >= E) return;
    int pos = atomicAdd(&cursor[dst[e]], 1);
    csr[pos] = src[e];
}

// =============================================================================
// Single-path GIN aggregation, neighbor loop unrolled by 2. Warp per node.
// out[i] = f( X[i] + sum_{j in N(i)} X[j] [+bias] ), f = LN+ReLU if LNR.
// =============================================================================
template<int D, bool LNR>
__global__ __launch_bounds__(256)
void gin_agg_kernel(const float* __restrict__ X,
                    const int* __restrict__ start, const int* __restrict__ cnt,
                    const int* __restrict__ csr,
                    const float* __restrict__ bias,
                    float* __restrict__ out, int Nrows)
{
    constexpr int C4 = D / 4;
    constexpr int V  = C4 / 32;
    int w = (int)((blockIdx.x * (long long)blockDim.x + threadIdx.x) >> 5);
    if (w >= Nrows) return;
    int lane = threadIdx.x & 31;

    float4 acc[V];
    #pragma unroll
    for (int v = 0; v < V; v++)
        acc[v] = *(const float4*)(X + (size_t)w * D + (lane + v * 32) * 4);

    int s0  = start[w];
    int deg = cnt[w];
    for (int base = 0; base < deg; base += 32) {
        int rem = deg - base;
        int myid = (lane < rem) ? csr[s0 + base + lane] : 0;
        int m = rem < 32 ? rem : 32;
        int k = 0;
        for (; k + 2 <= m; k += 2) {
            int j0 = __shfl_sync(0xffffffffu, myid, k);
            int j1 = __shfl_sync(0xffffffffu, myid, k + 1);
            const float* r0 = X + (size_t)j0 * D;
            const float* r1 = X + (size_t)j1 * D;
            #pragma unroll
            for (int v = 0; v < V; v++) {
                int c = (lane + v * 32) * 4;
                float4 t0 = *(const float4*)(r0 + c);
                float4 t1 = *(const float4*)(r1 + c);
                acc[v].x += t0.x + t1.x; acc[v].y += t0.y + t1.y;
                acc[v].z += t0.z + t1.z; acc[v].w += t0.w + t1.w;
            }
        }
        if (k < m) {
            int j = __shfl_sync(0xffffffffu, myid, k);
            const float* r = X + (size_t)j * D;
            #pragma unroll
            for (int v = 0; v < V; v++) {
                int c = (lane + v * 32) * 4;
                float4 t = *(const float4*)(r + c);
                acc[v].x += t.x; acc[v].y += t.y; acc[v].z += t.z; acc[v].w += t.w;
            }
        }
    }

    if (LNR) {
        float s = 0.f, sq = 0.f;
        #pragma unroll
        for (int v = 0; v < V; v++) {
            int c = (lane + v * 32) * 4;
            float4 b = *(const float4*)(bias + c);
            acc[v].x += b.x; acc[v].y += b.y; acc[v].z += b.z; acc[v].w += b.w;
            s  += acc[v].x + acc[v].y + acc[v].z + acc[v].w;
            sq += acc[v].x*acc[v].x + acc[v].y*acc[v].y
                + acc[v].z*acc[v].z + acc[v].w*acc[v].w;
        }
        #pragma unroll
        for (int off = 16; off; off >>= 1) {
            s  += __shfl_xor_sync(0xffffffffu, s,  off);
            sq += __shfl_xor_sync(0xffffffffu, sq, off);
        }
        float mean = s / D;
        float inv  = rsqrtf(sq / D - mean * mean + 1e-5f);
        #pragma unroll
        for (int v = 0; v < V; v++) {
            acc[v].x = fmaxf((acc[v].x - mean) * inv, 0.f);
            acc[v].y = fmaxf((acc[v].y - mean) * inv, 0.f);
            acc[v].z = fmaxf((acc[v].z - mean) * inv, 0.f);
            acc[v].w = fmaxf((acc[v].w - mean) * inv, 0.f);
        }
    }

    #pragma unroll
    for (int v = 0; v < V; v++)
        *(float4*)(out + (size_t)w * D + (lane + v * 32) * 4) = acc[v];
}

// =============================================================================
// Dual Z-dim (128) agg + bias + LN + ReLU. Working set 60 MB -> L2-safe.
// =============================================================================
__global__ __launch_bounds__(256)
void gin_agg_dualZ_kernel(const float* __restrict__ X1, const float* __restrict__ X2,
                          const int* __restrict__ start, const int* __restrict__ cnt,
                          const int* __restrict__ csr,
                          const float* __restrict__ bias,
                          float* __restrict__ out1, float* __restrict__ out2,
                          int Nrows)
{
    int w = (int)((blockIdx.x * (long long)blockDim.x + threadIdx.x) >> 5);
    if (w >= Nrows) return;
    int lane = threadIdx.x & 31;
    int c = lane * 4;

    float4 a1 = *(const float4*)(X1 + (size_t)w * Z_DIM + c);
    float4 a2 = *(const float4*)(X2 + (size_t)w * Z_DIM + c);

    int s0  = start[w];
    int deg = cnt[w];
    for (int base = 0; base < deg; base += 32) {
        int rem = deg - base;
        int myid = (lane < rem) ? csr[s0 + base + lane] : 0;
        int m = rem < 32 ? rem : 32;
        for (int k = 0; k < m; k++) {
            int j = __shfl_sync(0xffffffffu, myid, k);
            float4 t1 = *(const float4*)(X1 + (size_t)j * Z_DIM + c);
            float4 t2 = *(const float4*)(X2 + (size_t)j * Z_DIM + c);
            a1.x += t1.x; a1.y += t1.y; a1.z += t1.z; a1.w += t1.w;
            a2.x += t2.x; a2.y += t2.y; a2.z += t2.z; a2.w += t2.w;
        }
    }

    float4 b = *(const float4*)(bias + c);
    a1.x += b.x; a1.y += b.y; a1.z += b.z; a1.w += b.w;
    a2.x += b.x; a2.y += b.y; a2.z += b.z; a2.w += b.w;

    float s1 = a1.x + a1.y + a1.z + a1.w;
    float q1 = a1.x*a1.x + a1.y*a1.y + a1.z*a1.z + a1.w*a1.w;
    float s2 = a2.x + a2.y + a2.z + a2.w;
    float q2 = a2.x*a2.x + a2.y*a2.y + a2.z*a2.z + a2.w*a2.w;
    #pragma unroll
    for (int off = 16; off; off >>= 1) {
        s1 += __shfl_xor_sync(0xffffffffu, s1, off);
        q1 += __shfl_xor_sync(0xffffffffu, q1, off);
        s2 += __shfl_xor_sync(0xffffffffu, s2, off);
        q2 += __shfl_xor_sync(0xffffffffu, q2, off);
    }
    float m1 = s1 / Z_DIM, m2 = s2 / Z_DIM;
    float i1 = rsqrtf(q1 / Z_DIM - m1 * m1 + 1e-5f);
    float i2 = rsqrtf(q2 / Z_DIM - m2 * m2 + 1e-5f);

    float4 o1 = make_float4(fmaxf((a1.x - m1) * i1, 0.f), fmaxf((a1.y - m1) * i1, 0.f),
                            fmaxf((a1.z - m1) * i1, 0.f), fmaxf((a1.w - m1) * i1, 0.f));
    float4 o2 = make_float4(fmaxf((a2.x - m2) * i2, 0.f), fmaxf((a2.y - m2) * i2, 0.f),
                            fmaxf((a2.z - m2) * i2, 0.f), fmaxf((a2.w - m2) * i2, 0.f));
    *(float4*)(out1 + (size_t)w * Z_DIM + c) = o1;
    *(float4*)(out2 + (size_t)w * Z_DIM + c) = o2;
}

// ---- decoder L0: fused concat(zn|be) + agg -> aggd[144] ---------------------
__global__ __launch_bounds__(256)
void gin_agg_dec0_kernel(const float* __restrict__ zn, const float* __restrict__ be,
                         const int* __restrict__ start, const int* __restrict__ cnt,
                         const int* __restrict__ csr,
                         float* __restrict__ out, int Nrows)
{
    int w = (int)((blockIdx.x * (long long)blockDim.x + threadIdx.x) >> 5);
    if (w >= Nrows) return;
    int lane = threadIdx.x & 31;
    float4 accZ = *(const float4*)(zn + (size_t)w * Z_DIM + lane * 4);
    float4 accB = make_float4(0.f, 0.f, 0.f, 0.f);
    if (lane < 4) accB = *(const float4*)(be + (size_t)w * DB_DIM + lane * 4);

    int s0  = start[w];
    int deg = cnt[w];
    for (int base = 0; base < deg; base += 32) {
        int rem = deg - base;
        int myid = (lane < rem) ? csr[s0 + base + lane] : 0;
        int m = rem < 32 ? rem : 32;
        for (int k = 0; k < m; k++) {
            int j = __shfl_sync(0xffffffffu, myid, k);
            float4 t = *(const float4*)(zn + (size_t)j * Z_DIM + lane * 4);
            accZ.x += t.x; accZ.y += t.y; accZ.z += t.z; accZ.w += t.w;
            if (lane < 4) {
                float4 u = *(const float4*)(be + (size_t)j * DB_DIM + lane * 4);
                accB.x += u.x; accB.y += u.y; accB.z += u.z; accB.w += u.w;
            }
        }
    }
    *(float4*)(out + (size_t)w * DEC0_DIM + lane * 4) = accZ;
    if (lane < 4)
        *(float4*)(out + (size_t)w * DEC0_DIM + Z_DIM + lane * 4) = accB;
}

// ---------------- fused (Y + bias) -> LayerNorm -> ReLU ----------------------
template<int D>
__global__ __launch_bounds__(256)
void ln_relu_kernel(const float* __restrict__ Y, const float* __restrict__ bias,
                    float* __restrict__ out, int Nrows)
{
    constexpr int V = D / 128;
    int w = (int)((blockIdx.x * (long long)blockDim.x + threadIdx.x) >> 5);
    if (w >= Nrows) return;
    int lane = threadIdx.x & 31;

    float4 v[V];
    float s = 0.f, sq = 0.f;
    #pragma unroll
    for (int i = 0; i < V; i++) {
        int c = (lane + i * 32) * 4;
        float4 y = *(const float4*)(Y + (size_t)w * D + c);
        float4 b = *(const float4*)(bias + c);
        y.x += b.x; y.y += b.y; y.z += b.z; y.w += b.w;
        v[i] = y;
        s  += y.x + y.y + y.z + y.w;
        sq += y.x*y.x + y.y*y.y + y.z*y.z + y.w*y.w;
    }
    #pragma unroll
    for (int off = 16; off; off >>= 1) {
        s  += __shfl_xor_sync(0xffffffffu, s,  off);
        sq += __shfl_xor_sync(0xffffffffu, sq, off);
    }
    float mean = s / D;
    float inv  = rsqrtf(sq / D - mean * mean + 1e-5f);
    #pragma unroll
    for (int i = 0; i < V; i++) {
        int c = (lane + i * 32) * 4;
        float4 y = v[i];
        y.x = fmaxf((y.x - mean) * inv, 0.f);
        y.y = fmaxf((y.y - mean) * inv, 0.f);
        y.z = fmaxf((y.z - mean) * inv, 0.f);
        y.w = fmaxf((y.w - mean) * inv, 0.f);
        *(float4*)(out + (size_t)w * D + c) = y;
    }
}

// ---------------- dual subgraph mean pool (K=32, Z=128), 30MB set ------------
__global__ __launch_bounds__(256)
void pool_dual_kernel(const float* __restrict__ z1, const float* __restrict__ z2,
                      const int* __restrict__ idx,
                      float* __restrict__ o1, float* __restrict__ o2, int Nrows)
{
    int w = (int)((blockIdx.x * (long long)blockDim.x + threadIdx.x) >> 5);
    if (w >= Nrows) return;
    int lane = threadIdx.x & 31;
    int myidx = __ldg(&idx[(size_t)w * 32 + lane]);
    float4 a1 = make_float4(0.f, 0.f, 0.f, 0.f);
    float4 a2 = make_float4(0.f, 0.f, 0.f, 0.f);
    #pragma unroll
    for (int k = 0; k < 32; k++) {
        int j = __shfl_sync(0xffffffffu, myidx, k);
        float4 v1 = *(const float4*)(z1 + (size_t)j * 128 + lane * 4);
        float4 v2 = *(const float4*)(z2 + (size_t)j * 128 + lane * 4);
        a1.x += v1.x; a1.y += v1.y; a1.z += v1.z; a1.w += v1.w;
        a2.x += v2.x; a2.y += v2.y; a2.z += v2.z; a2.w += v2.w;
    }
    const float inv = 1.f / 32.f;
    a1.x *= inv; a1.y *= inv; a1.z *= inv; a1.w *= inv;
    a2.x *= inv; a2.y *= inv; a2.z *= inv; a2.w *= inv;
    *(float4*)(o1 + (size_t)w * 128 + lane * 4) = a1;
    *(float4*)(o2 + (size_t)w * 128 + lane * 4) = a2;
}

// ---------------- batch encoder MLP (8 -> 12 relu -> 16) ---------------------
__global__ __launch_bounds__(256)
void be_kernel(const float* __restrict__ bl,
               const float* __restrict__ W0, const float* __restrict__ b0,
               const float* __restrict__ W1, const float* __restrict__ b1,
               float* __restrict__ out, int Nr)
{
    int n = blockIdx.x * blockDim.x + threadIdx.x;
    if (n >= Nr) return;
    float in[8];
    #pragma unroll
    for (int i = 0; i < 8; i++) in[i] = bl[(size_t)n * 8 + i];
    float h[12];
    #pragma unroll
    for (int j = 0; j < 12; j++) {
        float s = b0[j];
        #pragma unroll
        for (int i = 0; i < 8; i++) s += in[i] * W0[i * 12 + j];
        h[j] = fmaxf(s, 0.f);
    }
    #pragma unroll
    for (int j = 0; j < 16; j++) {
        float s = b1[j];
        #pragma unroll
        for (int i = 0; i < 12; i++) s += h[i] * W1[i * 16 + j];
        out[(size_t)n * 16 + j] = s;
    }
}

// ---------------- batch discriminator: weights in smem, warp/node ------------
#define BD_BLOCKS 128
__global__ __launch_bounds__(256)
void bd_kernel(const float* __restrict__ zs,
               const float* __restrict__ W0, const float* __restrict__ b0,
               const float* __restrict__ W1, const float* __restrict__ b1,
               float* __restrict__ out, int Nr)
{
    __shared__ float W0s[128 * 64];
    __shared__ float W1s[64 * 8];
    __shared__ float b0s[64];
    int tid = threadIdx.x;
    for (int i = tid; i < 128 * 64; i += 256) W0s[i] = W0[i];
    for (int i = tid; i < 64 * 8;  i += 256) W1s[i] = W1[i];
    if (tid < 64) b0s[tid] = b0[tid];
    __syncthreads();

    int lane = tid & 31;
    int warp = tid >> 5;
    int gw   = blockIdx.x * 8 + warp;
    const int NW = BD_BLOCKS * 8;

    for (int n = gw; n < Nr; n += NW) {
        float zr[4];
        #pragma unroll
        for (int r = 0; r < 4; r++) zr[r] = zs[(size_t)n * 128 + r * 32 + lane];

        float h0 = b0s[lane], h1 = b0s[32 + lane];
        #pragma unroll 4
        for (int d = 0; d < 128; d++) {
            float zd = __shfl_sync(0xffffffffu, zr[d >> 5], d & 31);
            h0 += zd * W0s[d * 64 + lane];
            h1 += zd * W0s[d * 64 + 32 + lane];
        }
        h0 = fmaxf(h0, 0.f);
        h1 = fmaxf(h1, 0.f);

        float p[8];
        #pragma unroll
        for (int j = 0; j < 8; j++)
            p[j] = h0 * W1s[lane * 8 + j] + h1 * W1s[(32 + lane) * 8 + j];
        #pragma unroll
        for (int off = 16; off; off >>= 1)
            #pragma unroll
            for (int j = 0; j < 8; j++)
                p[j] += __shfl_xor_sync(0xffffffffu, p[j], off);
        if (lane < 8)
            out[(size_t)n * 8 + lane] = p[lane] + b1[lane];
    }
}

// ---------------- bilinear logits via precomputed Y = z_sub @ W --------------
__global__ __launch_bounds__(256)
void bil_dot_kernel(const float* __restrict__ Y, const float* __restrict__ zss,
                    const int* __restrict__ pos, const int* __restrict__ neg,
                    float* __restrict__ lp, float* __restrict__ ln_, int P)
{
    int w = (int)((blockIdx.x * (long long)blockDim.x + threadIdx.x) >> 5);
    if (w >= P) return;
    int lane = threadIdx.x & 31;
    int pi = __ldg(&pos[w]);
    int ni = __ldg(&neg[w]);
    float4 y = *(const float4*)(Y   + (size_t)pi * 128 + lane * 4);
    float4 a = *(const float4*)(zss + (size_t)pi * 128 + lane * 4);
    float4 b = *(const float4*)(zss + (size_t)ni * 128 + lane * 4);
    float sp = y.x * a.x + y.y * a.y + y.z * a.z + y.w * a.w;
    float sn = y.x * b.x + y.y * b.y + y.z * b.z + y.w * b.w;
    #pragma unroll
    for (int off = 16; off; off >>= 1) {
        sp += __shfl_xor_sync(0xffffffffu, sp, off);
        sn += __shfl_xor_sync(0xffffffffu, sn, off);
    }
    if (lane == 0) { lp[w] = sp; ln_[w] = sn; }
}

// =============================================================================
extern "C" void kernel_launch(void* const* d_in, const int* in_sizes, int n_in,
                              void* d_out, int out_size)
{
    const float* x      = (const float*)d_in[0];
    const float* x_shf  = (const float*)d_in[1];
    const float* bl     = (const float*)d_in[2];
    const float* enc_W0 = (const float*)d_in[3];
    const float* enc_b0 = (const float*)d_in[4];
    const float* enc_W1 = (const float*)d_in[5];
    const float* enc_b1 = (const float*)d_in[6];
    const float* dec_W0 = (const float*)d_in[7];
    const float* dec_b0 = (const float*)d_in[8];
    const float* dec_W1 = (const float*)d_in[9];
    const float* dec_b1 = (const float*)d_in[10];
    const float* be_W0  = (const float*)d_in[11];
    const float* be_b0  = (const float*)d_in[12];
    const float* be_W1  = (const float*)d_in[13];
    const float* be_b1  = (const float*)d_in[14];
    const float* bd_W0  = (const float*)d_in[15];
    const float* bd_b0  = (const float*)d_in[16];
    const float* bd_W1  = (const float*)d_in[17];
    const float* bd_b1  = (const float*)d_in[18];
    const float* bil_W  = (const float*)d_in[19];
    const int*   edge   = (const int*)d_in[20];
    const int*   subidx = (const int*)d_in[21];
    const int*   pos    = (const int*)d_in[22];
    const int*   neg    = (const int*)d_in[23];

    const int* src = edge;
    const int* dst = edge + N_EDGES;

    static float *bufA=nullptr,*bufB,*bufC,*bufC2,*bufD,*bufD2,*zn,*zn2,*be,*aggd;
    static int *cnt,*startp,*cursor,*csr;
    static cudaStream_t s1 = nullptr;
    static cudaEvent_t evPool = nullptr, evS1 = nullptr;
    if (!bufA) {
        cudaGetSymbolAddress((void**)&bufA,  g_bufA);
        cudaGetSymbolAddress((void**)&bufB,  g_bufB);
        cudaGetSymbolAddress((void**)&bufC,  g_bufC);
        cudaGetSymbolAddress((void**)&bufC2, g_bufC2);
        cudaGetSymbolAddress((void**)&bufD,  g_bufD);
        cudaGetSymbolAddress((void**)&bufD2, g_bufD2);
        cudaGetSymbolAddress((void**)&zn,    g_zn);
        cudaGetSymbolAddress((void**)&zn2,   g_zn2);
        cudaGetSymbolAddress((void**)&be,    g_be);
        cudaGetSymbolAddress((void**)&aggd,  g_aggd);
        cudaGetSymbolAddress((void**)&cnt,    g_cnt);
        cudaGetSymbolAddress((void**)&startp, g_start);
        cudaGetSymbolAddress((void**)&cursor, g_cursor);
        cudaGetSymbolAddress((void**)&csr,    g_csr);
        cudaFuncSetAttribute(mma_gemm_kernel,
                             cudaFuncAttributeMaxDynamicSharedMemorySize, GEMM_SMEM);
        cudaStreamCreateWithFlags(&s1, cudaStreamNonBlocking);
        cudaEventCreateWithFlags(&evPool, cudaEventDisableTiming);
        cudaEventCreateWithFlags(&evS1,   cudaEventDisableTiming);
    }

    float* out       = (float*)d_out;
    float* o_zsub    = out;
    float* o_zsubshf = out + (size_t)N_NODES * Z_DIM;
    float* o_recon   = out + 2ull * N_NODES * Z_DIM;
    float* o_lp      = o_recon + (size_t)N_NODES * IN_DIM;
    float* o_ln      = o_lp + P_PAIRS;
    float* o_lb      = o_ln + P_PAIRS;

    const int MB = (N_NODES + GBM - 1) / GBM;

    auto gemm = [&](int M, int Nn, int K, const float* A, const float* B,
                    const float* bias, float* C, cudaStream_t st) {
        dim3 grid(Nn / GBN, MB);
        mma_gemm_kernel<<<grid, 256, GEMM_SMEM, st>>>(M, Nn, K, A, B, bias, C);
    };

    // ---- CSR build (stream 0) ----
    cudaMemsetAsync(cnt, 0, N_NODES * sizeof(int), 0);
    hist_kernel<<<(N_EDGES + 255) / 256, 256>>>(dst, cnt, N_EDGES);
    scan_kernel<<<1, 1024>>>(cnt, startp, cursor, N_NODES);
    scatter_kernel<<<(N_EDGES + 255) / 256, 256>>>(src, dst, cursor, csr, N_EDGES);

    const int AGG_GRID = (N_NODES * 32 + 255) / 256;

    // batch encoder MLP (independent; cheap, stream 0 early)
    be_kernel<<<(N_NODES + 255) / 256, 256>>>(bl, be_W0, be_b0, be_W1, be_b1, be, N_NODES);

    // ---- encoder, both paths, serial on stream 0 (H-dim single-path aggs) ----
    gemm(N_NODES, H_DIM, IN_DIM, x, enc_W0, nullptr, bufA, 0);
    gin_agg_kernel<H_DIM, true><<<AGG_GRID, 256>>>(bufA, startp, cnt, csr, enc_b0, bufC, N_NODES);
    gemm(N_NODES, Z_DIM, H_DIM, bufC, enc_W1, nullptr, bufD, 0);

    gemm(N_NODES, H_DIM, IN_DIM, x_shf, enc_W0, nullptr, bufB, 0);
    gin_agg_kernel<H_DIM, true><<<AGG_GRID, 256>>>(bufB, startp, cnt, csr, enc_b0, bufC2, N_NODES);
    gemm(N_NODES, Z_DIM, H_DIM, bufC2, enc_W1, nullptr, bufD2, 0);

    // dual Z agg (60 MB working set, L2-safe) + dual pool
    gin_agg_dualZ_kernel<<<AGG_GRID, 256>>>(bufD, bufD2, startp, cnt, csr,
                                            enc_b1, zn, zn2, N_NODES);
    pool_dual_kernel<<<AGG_GRID, 256>>>(zn, zn2, subidx, o_zsub, o_zsubshf, N_NODES);
    cudaEventRecord(evPool, 0);

    // ---- side stream: bd + bilinear, overlapping the decoder chain ----
    cudaStreamWaitEvent(s1, evPool, 0);
    bd_kernel<<<BD_BLOCKS, 256, 0, s1>>>(o_zsub, bd_W0, bd_b0, bd_W1, bd_b1, o_lb, N_NODES);
    gemm(N_NODES, Z_DIM, Z_DIM, o_zsub, bil_W, nullptr, bufD, s1);
    bil_dot_kernel<<<(P_PAIRS * 32 + 255) / 256, 256, 0, s1>>>(bufD, o_zsubshf, pos, neg,
                                                               o_lp, o_ln, P_PAIRS);
    cudaEventRecord(evS1, s1);

    // ---- decoder on stream 0 ----
    gin_agg_dec0_kernel<<<AGG_GRID, 256>>>(zn, be, startp, cnt, csr, aggd, N_NODES);
    gemm(N_NODES, H_DIM, DEC0_DIM, aggd, dec_W0, nullptr, bufA, 0);
    ln_relu_kernel<H_DIM><<<AGG_GRID, 256>>>(bufA, dec_b0, bufC, N_NODES);
    gin_agg_kernel<H_DIM, false><<<AGG_GRID, 256>>>(bufC, startp, cnt, csr, nullptr, bufB, N_NODES);
    gemm(N_NODES, IN_DIM, H_DIM, bufB, dec_W1, dec_b1, o_recon, 0);

    // join side stream back into capture origin
    cudaStreamWaitEvent(0, evS1, 0);
}